// round 6
// baseline (speedup 1.0000x reference)
#include <cuda_runtime.h>

#define NN 32
#define MM 8
#define PP 16
#define BB 64
#define TT 128
#define NP1 33

// ---------------- global scratch ----------------
__device__ float g_muf[BB][TT][NN];
__device__ float g_mup[BB][TT][NN];
__device__ float g_Sigf[BB][TT][NN][NN];
__device__ float g_Sigp[BB][TT][NN][NN];
__device__ float g_J[BB][TT][NN][NN];    // t in [0, TT-2]
__device__ float g_G[BB][TT][NN][NN];    // Gs_t = Sigf_t - J Sigp_{t+1} J^T
__device__ float g_mb[BB][TT][NN];       // mb_t = muf_t - J mup_{t+1}
__device__ float g_CA[BB][TT][PP][NN];   // C_t @ A_t
__device__ float g_CCt[BB][TT][PP][PP];  // C_t @ C_t^T

__device__ __forceinline__ void bar_g(int id) {
    asm volatile("bar.sync %0, %1;" :: "r"(id), "r"(256) : "memory");
}

// ===== prep: CA = C@A, CCt = C@C^T for all (b,t) — fully parallel =====
__global__ void __launch_bounds__(256) prep_kernel(
    const float* __restrict__ A, const float* __restrict__ C)
{
    const int t = blockIdx.x, b = blockIdx.y;
    const int tid = threadIdx.x;
    __shared__ float sA[NN][NN + 1], sC[PP][NN + 1];
    const float* Ab = A + ((size_t)b * TT + t) * NN * NN;
    const float* Cb = C + ((size_t)b * TT + t) * PP * NN;
    for (int idx = tid; idx < NN * NN; idx += 256) sA[idx >> 5][idx & 31] = Ab[idx];
    for (int idx = tid; idx < PP * NN; idx += 256) sC[idx >> 5][idx & 31] = Cb[idx];
    __syncthreads();
    {
        const int c = tid & 15, r = tid >> 4;
        float a0 = 0.f, a1 = 0.f;
        #pragma unroll
        for (int k = 0; k < NN; ++k) {
            const float cv = sC[r][k];
            a0 += cv * sA[k][c]; a1 += cv * sA[k][c + 16];
        }
        g_CA[b][t][r][c] = a0; g_CA[b][t][r][c + 16] = a1;
    }
    {
        const int c = tid & 15, r = tid >> 4;
        float cc = 0.f;
        #pragma unroll
        for (int k = 0; k < NN; ++k) cc += sC[r][k] * sC[c][k];
        g_CCt[b][t][r][c] = cc;
    }
}

// ================= forward filter: 1 CTA / batch, 512 threads =================
// g0 (warps 0-7):  tmp = A@Sig -> Sigp = tmp@A^T        (named barrier 1)
// g1 (warps 8-15): E = CA@Sig -> CS,S0 -> GJ | prefetch (named barrier 2)
// join (full barrier) -> Sigf = Sigp - K@CS (ALL warps) -> end barrier
__global__ void __launch_bounds__(512) fwd_kernel(
    const float* __restrict__ Y, const float* __restrict__ U,
    const float* __restrict__ A, const float* __restrict__ Bm,
    const float* __restrict__ C, const float* __restrict__ mu0,
    const float* __restrict__ Sigma0)
{
    const int b = blockIdx.x;
    const int tid = threadIdx.x;
    const int lane = tid & 31, wid = tid >> 5;
    const int g = tid >> 8;

    __shared__ float sA[2][NN][NN + 1];
    __shared__ float sC[2][PP][NN + 1];
    __shared__ float sCA[2][PP][NN + 1];
    __shared__ float sCCt[2][PP][PP + 1];
    __shared__ float sB[2][NN][MM + 1];
    __shared__ float sy[2][PP], su[2][MM];
    __shared__ float sSig[NN][NN + 1], sTmp[NN][NN + 1], sSigp[NN][NN + 1];
    __shared__ float sE[PP][NN + 1], sCS[PP][NN + 1], sS0[PP][PP + 1], sK[NN][PP + 1];
    __shared__ float smu[NN], smup[NN], sr[PP];

    const float* Ab = A  + (size_t)b * TT * NN * NN;
    const float* Cb = C  + (size_t)b * TT * PP * NN;
    const float* Bb = Bm + (size_t)b * TT * NN * MM;
    const float* Yb = Y  + (size_t)b * TT * PP;
    const float* Ub = U  + (size_t)b * TT * MM;

    // init: carry + buffer 0
    for (int idx = tid; idx < NN * NN; idx += 512) {
        sSig[idx >> 5][idx & 31]  = Sigma0[idx];
        sA[0][idx >> 5][idx & 31] = Ab[idx];
    }
    for (int idx = tid; idx < PP * NN; idx += 512) {
        sC[0][idx >> 5][idx & 31]  = Cb[idx];
        sCA[0][idx >> 5][idx & 31] = g_CA[b][0][idx >> 5][idx & 31];
    }
    if (tid < PP * PP) sCCt[0][tid >> 4][tid & 15] = g_CCt[b][0][tid >> 4][tid & 15];
    if (tid < NN * MM) sB[0][tid >> 3][tid & 7] = Bb[tid];
    if (tid < NN) smu[tid] = mu0[tid];
    if (tid < PP) sy[0][tid] = Yb[tid];
    else if (tid < PP + MM) su[0][tid - PP] = Ub[tid - PP];
    __syncthreads();

    for (int t = 0; t < TT; ++t) {
        const int cur = t & 1, nxt = cur ^ 1;

        if (g == 0) {
            // ---- g0 phase 1: tmp = A @ Sig (2x2 tiles, 256 threads) ----
            {
                const int tx = tid & 15, ty = tid >> 4;
                float a00 = 0.f, a01 = 0.f, a10 = 0.f, a11 = 0.f;
                #pragma unroll
                for (int k = 0; k < NN; ++k) {
                    const float l0 = sA[cur][ty][k],   l1 = sA[cur][ty + 16][k];
                    const float r0 = sSig[k][tx], r1 = sSig[k][tx + 16];
                    a00 += l0 * r0; a01 += l0 * r1; a10 += l1 * r0; a11 += l1 * r1;
                }
                sTmp[ty][tx] = a00;      sTmp[ty][tx + 16] = a01;
                sTmp[ty + 16][tx] = a10; sTmp[ty + 16][tx + 16] = a11;
            }
            bar_g(1);
            // ---- g0 phase 2: Sigp = tmp @ A^T + Q ----
            {
                const int tx = tid & 15, ty = tid >> 4;
                float a00 = 0.f, a01 = 0.f, a10 = 0.f, a11 = 0.f;
                #pragma unroll
                for (int k = 0; k < NN; ++k) {
                    const float l0 = sTmp[ty][k],    l1 = sTmp[ty + 16][k];
                    const float r0 = sA[cur][tx][k], r1 = sA[cur][tx + 16][k];
                    a00 += l0 * r0; a01 += l0 * r1; a10 += l1 * r0; a11 += l1 * r1;
                }
                const float q = (ty == tx) ? 0.01f : 0.f;
                a00 += q; a11 += q;
                sSigp[ty][tx] = a00;      sSigp[ty][tx + 16] = a01;
                sSigp[ty + 16][tx] = a10; sSigp[ty + 16][tx + 16] = a11;
                float* gp = &g_Sigp[b][t][0][0];
                gp[ty * NN + tx] = a00;        gp[ty * NN + tx + 16] = a01;
                gp[(ty + 16) * NN + tx] = a10; gp[(ty + 16) * NN + tx + 16] = a11;
            }
        } else {
            const int l = tid - 256;     // 0..255
            // ---- g1 phase 1: E = CA @ Sig ; warp8 tail: mup ----
            {
                const int c = l & 15, r = l >> 4;
                float a0 = 0.f, a1 = 0.f;
                #pragma unroll
                for (int k = 0; k < NN; ++k) {
                    const float cv = sCA[cur][r][k];
                    a0 += cv * sSig[k][c]; a1 += cv * sSig[k][c + 16];
                }
                sE[r][c] = a0; sE[r][c + 16] = a1;
            }
            if (l < NN) {
                float m = 0.f;
                #pragma unroll
                for (int k = 0; k < NN; ++k) m += sA[cur][l][k] * smu[k];
                #pragma unroll
                for (int k = 0; k < MM; ++k) m += sB[cur][l][k] * su[cur][k];
                smup[l] = m;
            }
            bar_g(2);
            // ---- g1 phase 2: CS = E@A^T + 0.01C ; S0 = E@CA^T + 0.01CCt ; r ----
            {
                const int c = l & 15, r = l >> 4;
                float cs0 = 0.f, cs1 = 0.f, s0 = 0.f;
                #pragma unroll
                for (int k = 0; k < NN; ++k) {
                    const float e = sE[r][k];
                    cs0 += e * sA[cur][c][k];
                    cs1 += e * sA[cur][c + 16][k];
                    s0  += e * sCA[cur][c][k];
                }
                sCS[r][c]      = cs0 + 0.01f * sC[cur][r][c];
                sCS[r][c + 16] = cs1 + 0.01f * sC[cur][r][c + 16];
                sS0[r][c]      = s0  + 0.01f * sCCt[cur][r][c];
            }
            if (l < PP) {
                float m = 0.f;
                #pragma unroll
                for (int k = 0; k < NN; ++k) m += sC[cur][l][k] * smup[k];
                sr[l] = sy[cur][l] - m;
            }
            bar_g(2);
            // ---- g1 phase 3: warp8 GJ -> K ; warps 9-15 prefetch ----
            if (wid == 8) {
                float colA[PP], colB[PP];
                #pragma unroll
                for (int i = 0; i < PP; ++i) {
                    colA[i] = (lane < PP)
                        ? 0.5f * (sS0[i][lane] + sS0[lane][i]) + ((i == lane) ? 0.01f : 0.f)
                        : sCS[i][lane - PP];
                    colB[i] = (lane < PP) ? sCS[i][PP + lane] : 0.f;
                }
                #pragma unroll
                for (int k = 0; k < PP; ++k) {
                    float f[PP];
                    #pragma unroll
                    for (int i = 0; i < PP; ++i) f[i] = __shfl_sync(0xffffffffu, colA[i], k);
                    const float pr = 1.0f / f[k];
                    #pragma unroll
                    for (int i = 0; i < PP; ++i) {
                        if (i != k) {
                            const float gg = f[i] * pr;
                            colA[i] -= gg * colA[k];
                            colB[i] -= gg * colB[k];
                        }
                    }
                    colA[k] *= pr; colB[k] *= pr;
                }
                if (lane >= PP) {
                    #pragma unroll
                    for (int i = 0; i < PP; ++i) sK[lane - PP][i] = colA[i];
                } else {
                    #pragma unroll
                    for (int i = 0; i < PP; ++i) sK[PP + lane][i] = colB[i];
                }
            } else if (t + 1 < TT) {
                const int wt = tid - 288;   // 0..223
                const float* An = Ab + (size_t)(t + 1) * NN * NN;
                const float* Cn = Cb + (size_t)(t + 1) * PP * NN;
                const float* Bn = Bb + (size_t)(t + 1) * NN * MM;
                for (int idx = wt; idx < NN * NN; idx += 224) sA[nxt][idx >> 5][idx & 31] = An[idx];
                for (int idx = wt; idx < PP * NN; idx += 224) {
                    sC[nxt][idx >> 5][idx & 31]  = Cn[idx];
                    sCA[nxt][idx >> 5][idx & 31] = g_CA[b][t + 1][idx >> 5][idx & 31];
                }
                for (int idx = wt; idx < PP * PP; idx += 224)
                    sCCt[nxt][idx >> 4][idx & 15] = g_CCt[b][t + 1][idx >> 4][idx & 15];
                for (int idx = wt; idx < NN * MM; idx += 224) sB[nxt][idx >> 3][idx & 7] = Bn[idx];
                if (wt < PP) sy[nxt][wt] = Yb[(t + 1) * PP + wt];
                else if (wt < PP + MM) su[nxt][wt - PP] = Ub[(t + 1) * MM + (wt - PP)];
            }
        }
        __syncthreads();   // join: K (g1) meets Sigp (g0)

        // ---- P5 (ALL 16 warps): Sig_f = Sigp - K@CS ; write carry AND stash ----
        {
            const int i0 = wid, j = lane;   // i0 in 0..15, rows i0 and i0+16
            float x0 = sSigp[i0][j], x1 = sSigp[i0 + 16][j];
            #pragma unroll
            for (int k = 0; k < PP; ++k) {
                const float c = sCS[k][j];
                x0 -= sK[i0][k] * c; x1 -= sK[i0 + 16][k] * c;
            }
            sSig[i0][j] = x0; sSig[i0 + 16][j] = x1;
            float* gf = &g_Sigf[b][t][0][0];
            gf[i0 * NN + j] = x0; gf[(i0 + 16) * NN + j] = x1;
        }
        if (tid < NN) {
            float m = smup[tid];
            #pragma unroll
            for (int k = 0; k < PP; ++k) m += sK[tid][k] * sr[k];
            smu[tid] = m;
            g_muf[b][t][tid] = m;
            g_mup[b][t][tid] = smup[tid];
        }
        __syncthreads();
    }
}

// ===== smoother gains + backward constants (fully parallel over b,t) =====
__global__ void __launch_bounds__(256) jgain_kernel(const float* __restrict__ A)
{
    const int t = blockIdx.x;     // 0..TT-2
    const int b = blockIdx.y;
    const int tid = threadIdx.x;
    const int tx = tid & 15, ty = tid >> 4;

    __shared__ float sSf[NN][NN + 1], sA[NN][NN + 1], sX[NN][NN + 1], sT2[NN][NN + 1];
    __shared__ float prow[2][2 * NN];
    __shared__ float sf[2][NN];
    __shared__ float smp1[NN];

    const float* Ab = A + ((size_t)b * TT + t) * NN * NN;
    for (int idx = tid; idx < NN * NN; idx += 256) {
        sSf[idx >> 5][idx & 31] = g_Sigf[b][t][idx >> 5][idx & 31];
        sA[idx >> 5][idx & 31]  = Ab[idx];
    }
    if (tid < NN) smp1[tid] = g_mup[b][t + 1][tid];
    __syncthreads();

    // X = Sigf @ A^T
    {
        float a00 = 0.f, a01 = 0.f, a10 = 0.f, a11 = 0.f;
        #pragma unroll
        for (int k = 0; k < NN; ++k) {
            const float l0 = sSf[ty][k], l1 = sSf[ty + 16][k];
            const float r0 = sA[tx][k],  r1 = sA[tx + 16][k];
            a00 += l0 * r0; a01 += l0 * r1; a10 += l1 * r0; a11 += l1 * r1;
        }
        sX[ty][tx] = a00;      sX[ty][tx + 16] = a01;
        sX[ty + 16][tx] = a10; sX[ty + 16][tx + 16] = a11;
    }
    __syncthreads();

    // Gauss-Jordan on [Sigp_{t+1} | X^T]
    const int row = tid >> 3;
    const int c0  = (tid & 7) * 8;
    float r8[8];
    if (c0 < NN) {
        #pragma unroll
        for (int m = 0; m < 8; ++m) r8[m] = g_Sigp[b][t + 1][row][c0 + m];
    } else {
        #pragma unroll
        for (int m = 0; m < 8; ++m) r8[m] = sX[c0 - NN + m][row];   // X^T
    }
    #pragma unroll
    for (int k = 0; k < NN; ++k) {
        const int pb = k & 1;
        if (row == k) {
            #pragma unroll
            for (int m = 0; m < 8; ++m) prow[pb][c0 + m] = r8[m];
        }
        if ((tid & 7) == (k >> 3)) sf[pb][row] = r8[k & 7];
        __syncthreads();
        const float pr = 1.0f / prow[pb][k];
        if (row == k) {
            #pragma unroll
            for (int m = 0; m < 8; ++m) r8[m] *= pr;
        } else {
            const float g = sf[pb][row] * pr;
            #pragma unroll
            for (int m = 0; m < 8; ++m) r8[m] -= g * prow[pb][c0 + m];
        }
    }
    __syncthreads();
    if (c0 >= NN) {
        #pragma unroll
        for (int m = 0; m < 8; ++m) sX[c0 - NN + m][row] = r8[m];   // J
    }
    __syncthreads();
    for (int idx = tid; idx < NN * NN; idx += 256) {
        g_J[b][t][idx >> 5][idx & 31] = sX[idx >> 5][idx & 31];
        sA[idx >> 5][idx & 31] = g_Sigp[b][t + 1][idx >> 5][idx & 31];
    }
    __syncthreads();

    // T2 = J @ Sigp_{t+1}
    {
        float a00 = 0.f, a01 = 0.f, a10 = 0.f, a11 = 0.f;
        #pragma unroll
        for (int k = 0; k < NN; ++k) {
            const float l0 = sX[ty][k], l1 = sX[ty + 16][k];
            const float r0 = sA[k][tx], r1 = sA[k][tx + 16];
            a00 += l0 * r0; a01 += l0 * r1; a10 += l1 * r0; a11 += l1 * r1;
        }
        sT2[ty][tx] = a00;      sT2[ty][tx + 16] = a01;
        sT2[ty + 16][tx] = a10; sT2[ty + 16][tx + 16] = a11;
    }
    __syncthreads();

    // G = Sf - T2 @ J^T ; mb = muf - J mp1
    {
        float e00 = 0.f, e01 = 0.f, e10 = 0.f, e11 = 0.f;
        #pragma unroll
        for (int k = 0; k < NN; ++k) {
            const float t0 = sT2[ty][k], t1 = sT2[ty + 16][k];
            const float j0 = sX[tx][k],  j1 = sX[tx + 16][k];
            e00 += t0 * j0; e01 += t0 * j1; e10 += t1 * j0; e11 += t1 * j1;
        }
        float* gg = &g_G[b][t][0][0];
        gg[ty * NN + tx]             = sSf[ty][tx]           - e00;
        gg[ty * NN + tx + 16]        = sSf[ty][tx + 16]      - e01;
        gg[(ty + 16) * NN + tx]      = sSf[ty + 16][tx]      - e10;
        gg[(ty + 16) * NN + tx + 16] = sSf[ty + 16][tx + 16] - e11;
    }
    if (tid < NN) {
        float m = g_muf[b][t][tid];
        #pragma unroll
        for (int k = 0; k < NN; ++k) m -= sX[tid][k] * smp1[k];
        g_mb[b][t][tid] = m;
    }
}

// ========== backward RTS: Sig_s = G + J Sig_s J^T ; mu = mb + J mu ==========
__global__ void __launch_bounds__(512) bwd_kernel(float* __restrict__ out)
{
    const int b = blockIdx.x;
    const int tid = threadIdx.x;
    const int j  = tid & 31;
    const int i0 = tid >> 5;

    __shared__ float sJ[2][NN][NN + 1], sTmp[NN][NN + 1], sSig[NN][NN + 1];
    __shared__ float smu[NN];

    {
        const float v0 = g_Sigf[b][TT - 1][i0][j];
        const float v1 = g_Sigf[b][TT - 1][i0 + 16][j];
        sSig[i0][j] = v0; sSig[i0 + 16][j] = v1;
        const size_t base = ((size_t)b * TT + (TT - 1)) * NN;
        out[(base + i0) * NP1 + 1 + j] = v0;
        out[(base + i0 + 16) * NP1 + 1 + j] = v1;
        if (tid < NN) {
            const float m = g_muf[b][TT - 1][tid];
            smu[tid] = m;
            out[(base + tid) * NP1] = m;
        }
    }
    float pG0 = g_G[b][TT - 2][i0][j];
    float pG1 = g_G[b][TT - 2][i0 + 16][j];
    sJ[0][i0][j]      = g_J[b][TT - 2][i0][j];
    sJ[0][i0 + 16][j] = g_J[b][TT - 2][i0 + 16][j];
    __syncthreads();

    int cur = 0;
    for (int t = TT - 2; t >= 0; --t) {
        float a0 = 0.f, a1 = 0.f;
        #pragma unroll
        for (int k = 0; k < NN; ++k) {
            const float r = sSig[k][j];
            a0 += sJ[cur][i0][k] * r; a1 += sJ[cur][i0 + 16][k] * r;
        }
        sTmp[i0][j] = a0; sTmp[i0 + 16][j] = a1;

        float m = 0.f;
        if (tid < NN) {
            m = g_mb[b][t][tid];
            #pragma unroll
            for (int k = 0; k < NN; ++k) m += sJ[cur][tid][k] * smu[k];
        }
        float nJ0 = 0.f, nJ1 = 0.f, nG0 = 0.f, nG1 = 0.f;
        if (t > 0) {
            nJ0 = g_J[b][t - 1][i0][j];     nJ1 = g_J[b][t - 1][i0 + 16][j];
            nG0 = g_G[b][t - 1][i0][j];     nG1 = g_G[b][t - 1][i0 + 16][j];
        }
        __syncthreads();

        {
            float e0 = 0.f, e1 = 0.f;
            #pragma unroll
            for (int k = 0; k < NN; ++k) {
                const float jj = sJ[cur][j][k];
                e0 += sTmp[i0][k] * jj; e1 += sTmp[i0 + 16][k] * jj;
            }
            const float v0 = pG0 + e0;
            const float v1 = pG1 + e1;
            sSig[i0][j] = v0; sSig[i0 + 16][j] = v1;
            const size_t base = ((size_t)b * TT + t) * NN;
            out[(base + i0) * NP1 + 1 + j] = v0;
            out[(base + i0 + 16) * NP1 + 1 + j] = v1;
            if (tid < NN) {
                smu[tid] = m;
                out[(base + tid) * NP1] = m;
            }
        }
        if (t > 0) {
            sJ[cur ^ 1][i0][j] = nJ0; sJ[cur ^ 1][i0 + 16][j] = nJ1;
            pG0 = nG0; pG1 = nG1;
        }
        __syncthreads();
        cur ^= 1;
    }
}

// ---------------- launch ----------------
extern "C" void kernel_launch(void* const* d_in, const int* in_sizes, int n_in,
                              void* d_out, int out_size)
{
    const float* Y      = (const float*)d_in[0];
    const float* U      = (const float*)d_in[1];
    const float* A      = (const float*)d_in[2];
    const float* Bm     = (const float*)d_in[3];
    const float* C      = (const float*)d_in[4];
    const float* mu0    = (const float*)d_in[5];
    const float* Sigma0 = (const float*)d_in[6];
    float* out = (float*)d_out;

    prep_kernel<<<dim3(TT, BB), 256>>>(A, C);
    fwd_kernel<<<BB, 512>>>(Y, U, A, Bm, C, mu0, Sigma0);
    jgain_kernel<<<dim3(TT - 1, BB), 256>>>(A);
    bwd_kernel<<<BB, 512>>>(out);
}

// round 7
// speedup vs baseline: 1.2974x; 1.2974x over previous
#include <cuda_runtime.h>

#define NN 32
#define MM 8
#define PP 16
#define BB 64
#define TT 128
#define NP1 33

// ---------------- global scratch ----------------
__device__ float g_muf[BB][TT][NN];
__device__ float g_mup[BB][TT][NN];
__device__ float g_Sigf[BB][TT][NN][NN];
__device__ float g_Sigp[BB][TT][NN][NN];
__device__ float g_J[BB][TT][NN][NN];    // t in [0, TT-2]
__device__ float g_G[BB][TT][NN][NN];    // Gs_t = Sigf_t - J Sigp_{t+1} J^T
__device__ float g_mb[BB][TT][NN];       // mb_t = muf_t - J mup_{t+1}
// stride-2 composites at odd t (1,3,...,125)
__device__ float g_J2[BB][TT][NN][NN];
__device__ float g_G2[BB][TT][NN][NN];
__device__ float g_mb2[BB][TT][NN];
// stride-4 composites at t = 3 mod 4 (3,7,...,123)
__device__ float g_J4[BB][TT][NN][NN];
__device__ float g_G4[BB][TT][NN][NN];
__device__ float g_mb4[BB][TT][NN];
// smoothed results needed by fill passes
__device__ float g_Sigs[BB][TT][NN][NN];
__device__ float g_mus[BB][TT][NN];

// ================= forward filter: 1 CTA / batch, 512 threads (R4) =================
__global__ void __launch_bounds__(512) fwd_kernel(
    const float* __restrict__ Y, const float* __restrict__ U,
    const float* __restrict__ A, const float* __restrict__ Bm,
    const float* __restrict__ C, const float* __restrict__ mu0,
    const float* __restrict__ Sigma0)
{
    const int b = blockIdx.x;
    const int tid = threadIdx.x;
    const int lane = tid & 31, wid = tid >> 5;
    const int g  = tid >> 8;          // 0 or 1
    const int t8 = tid & 255;
    const int tx = t8 & 15;
    const int ty = t8 >> 4;           // 0..15

    __shared__ float sA[NN][NN + 1], sC[PP][NN + 1], sB[NN][MM + 1];
    __shared__ float sSig[NN][NN + 1], sTmp[NN][NN + 1], sSigp[NN][NN + 1];
    __shared__ float sH[PP][NN + 1], sCS[PP][NN + 1], sS0[PP][PP + 1], sK[NN][PP + 1];
    __shared__ float sCA[PP][NN + 1], sCCt[PP][PP + 1];
    __shared__ float smu[NN], smup[NN], sr[PP], sy[PP], su[MM];

    const float* Ab = A  + (size_t)b * TT * NN * NN;
    const float* Cb = C  + (size_t)b * TT * PP * NN;
    const float* Bb = Bm + (size_t)b * TT * NN * MM;
    const float* Yb = Y  + (size_t)b * TT * PP;
    const float* Ub = U  + (size_t)b * TT * MM;

    for (int idx = tid; idx < NN * NN; idx += 512) {
        sSig[idx >> 5][idx & 31] = Sigma0[idx];
        sA[idx >> 5][idx & 31]   = Ab[idx];
    }
    for (int idx = tid; idx < PP * NN; idx += 512) sC[idx >> 5][idx & 31] = Cb[idx];
    if (tid < NN * MM) sB[tid >> 3][tid & 7] = Bb[tid];
    if (tid < NN) smu[tid] = mu0[tid];
    if (tid < PP) sy[tid] = Yb[tid];
    else if (tid < PP + MM) su[tid - PP] = Ub[tid - PP];
    __syncthreads();

    for (int t = 0; t < TT; ++t) {
        // ==== P1: g0: tmp = A@Sig (2x2) | g1: CA = C@A, CCt = C@C^T | mup ====
        if (g == 0) {
            float a00 = 0.f, a01 = 0.f, a10 = 0.f, a11 = 0.f;
            #pragma unroll
            for (int k = 0; k < NN; ++k) {
                const float l0 = sA[ty][k],   l1 = sA[ty + 16][k];
                const float r0 = sSig[k][tx], r1 = sSig[k][tx + 16];
                a00 += l0 * r0; a01 += l0 * r1; a10 += l1 * r0; a11 += l1 * r1;
            }
            sTmp[ty][tx] = a00;      sTmp[ty][tx + 16] = a01;
            sTmp[ty + 16][tx] = a10; sTmp[ty + 16][tx + 16] = a11;
        } else {
            float ca0 = 0.f, ca1 = 0.f, cc = 0.f;
            #pragma unroll
            for (int k = 0; k < NN; ++k) {
                const float c = sC[ty][k];
                ca0 += c * sA[k][tx]; ca1 += c * sA[k][tx + 16];
                cc  += c * sC[tx][k];
            }
            sCA[ty][tx] = ca0; sCA[ty][tx + 16] = ca1;
            sCCt[ty][tx] = cc;
            if (tid >= 480) {
                const int l = tid - 480;
                float m = 0.f;
                #pragma unroll
                for (int k = 0; k < NN; ++k) m += sA[l][k] * smu[k];
                #pragma unroll
                for (int k = 0; k < MM; ++k) m += sB[l][k] * su[k];
                smup[l] = m;
            }
        }
        __syncthreads();

        // ==== P2: g0: Sigp = tmp@A^T + Q | g1: H = C@tmp | r ====
        if (g == 0) {
            float a00 = 0.f, a01 = 0.f, a10 = 0.f, a11 = 0.f;
            #pragma unroll
            for (int k = 0; k < NN; ++k) {
                const float l0 = sTmp[ty][k],  l1 = sTmp[ty + 16][k];
                const float r0 = sA[tx][k],    r1 = sA[tx + 16][k];
                a00 += l0 * r0; a01 += l0 * r1; a10 += l1 * r0; a11 += l1 * r1;
            }
            const float q = (ty == tx) ? 0.01f : 0.f;
            a00 += q; a11 += q;
            sSigp[ty][tx] = a00;      sSigp[ty][tx + 16] = a01;
            sSigp[ty + 16][tx] = a10; sSigp[ty + 16][tx + 16] = a11;
            float* gp = &g_Sigp[b][t][0][0];
            gp[ty * NN + tx] = a00;        gp[ty * NN + tx + 16] = a01;
            gp[(ty + 16) * NN + tx] = a10; gp[(ty + 16) * NN + tx + 16] = a11;
        } else {
            float h0 = 0.f, h1 = 0.f;
            #pragma unroll
            for (int k = 0; k < NN; ++k) {
                const float c = sC[ty][k];
                h0 += c * sTmp[k][tx]; h1 += c * sTmp[k][tx + 16];
            }
            sH[ty][tx] = h0; sH[ty][tx + 16] = h1;
            if (tid >= 480 && tid < 480 + PP) {
                const int i = tid - 480;
                float m = 0.f;
                #pragma unroll
                for (int k = 0; k < NN; ++k) m += sC[i][k] * smup[k];
                sr[i] = sy[i] - m;
            }
        }
        __syncthreads();

        // ==== P3: g0: CS = H@A^T + 0.01C | g1: S0 = H@CA^T + 0.01 CCt ====
        if (g == 0) {
            float cs0 = 0.f, cs1 = 0.f;
            #pragma unroll
            for (int k = 0; k < NN; ++k) {
                const float h = sH[ty][k];
                cs0 += h * sA[tx][k]; cs1 += h * sA[tx + 16][k];
            }
            sCS[ty][tx]      = cs0 + 0.01f * sC[ty][tx];
            sCS[ty][tx + 16] = cs1 + 0.01f * sC[ty][tx + 16];
        } else {
            float s0 = 0.f;
            #pragma unroll
            for (int k = 0; k < NN; ++k) s0 += sH[ty][k] * sCA[tx][k];
            sS0[ty][tx] = s0 + 0.01f * sCCt[ty][tx];
        }
        __syncthreads();

        // ==== P4: warp0 GJ on [sym(S0)+R | CS] -> K ; warps 1-15 prefetch ====
        if (wid == 0) {
            float colA[PP], colB[PP];
            #pragma unroll
            for (int i = 0; i < PP; ++i) {
                colA[i] = (lane < PP)
                    ? 0.5f * (sS0[i][lane] + sS0[lane][i]) + ((i == lane) ? 0.01f : 0.f)
                    : sCS[i][lane - PP];
                colB[i] = (lane < PP) ? sCS[i][PP + lane] : 0.f;
            }
            #pragma unroll
            for (int k = 0; k < PP; ++k) {
                float f[PP];
                #pragma unroll
                for (int i = 0; i < PP; ++i) f[i] = __shfl_sync(0xffffffffu, colA[i], k);
                const float pr = 1.0f / f[k];
                #pragma unroll
                for (int i = 0; i < PP; ++i) {
                    if (i != k) {
                        const float gg = f[i] * pr;
                        colA[i] -= gg * colA[k];
                        colB[i] -= gg * colB[k];
                    }
                }
                colA[k] *= pr; colB[k] *= pr;
            }
            if (lane >= PP) {
                #pragma unroll
                for (int i = 0; i < PP; ++i) sK[lane - PP][i] = colA[i];
            } else {
                #pragma unroll
                for (int i = 0; i < PP; ++i) sK[PP + lane][i] = colB[i];
            }
        } else if (t + 1 < TT) {
            const int wt = tid - 32;
            const float* An = Ab + (size_t)(t + 1) * NN * NN;
            const float* Cn = Cb + (size_t)(t + 1) * PP * NN;
            const float* Bn = Bb + (size_t)(t + 1) * NN * MM;
            for (int idx = wt; idx < NN * NN; idx += 480) sA[idx >> 5][idx & 31] = An[idx];
            for (int idx = wt; idx < PP * NN; idx += 480) sC[idx >> 5][idx & 31] = Cn[idx];
            for (int idx = wt; idx < NN * MM; idx += 480) sB[idx >> 3][idx & 7] = Bn[idx];
            if (wt < PP) sy[wt] = Yb[(t + 1) * PP + wt];
            else if (wt < PP + MM) su[wt - PP] = Ub[(t + 1) * MM + (wt - PP)];
        }
        __syncthreads();

        // ==== P5: Sig_f = Sigp - K@CS (algebraically symmetric); mu_f ====
        {
            const int i0 = wid, j = lane;
            float x0 = sSigp[i0][j], x1 = sSigp[i0 + 16][j];
            #pragma unroll
            for (int k = 0; k < PP; ++k) {
                const float c = sCS[k][j];
                x0 -= sK[i0][k] * c; x1 -= sK[i0 + 16][k] * c;
            }
            sSig[i0][j] = x0; sSig[i0 + 16][j] = x1;
            float* gf = &g_Sigf[b][t][0][0];
            gf[i0 * NN + j] = x0; gf[(i0 + 16) * NN + j] = x1;
        }
        if (tid < NN) {
            float m = smup[tid];
            #pragma unroll
            for (int k = 0; k < PP; ++k) m += sK[tid][k] * sr[k];
            smu[tid] = m;
            g_muf[b][t][tid] = m;
            g_mup[b][t][tid] = smup[tid];
        }
        __syncthreads();
    }
}

// ===== smoother gains + backward constants (fully parallel over b,t) — R4 =====
__global__ void __launch_bounds__(256) jgain_kernel(const float* __restrict__ A)
{
    const int t = blockIdx.x;     // 0..TT-2
    const int b = blockIdx.y;
    const int tid = threadIdx.x;
    const int tx = tid & 15, ty = tid >> 4;

    __shared__ float sSf[NN][NN + 1], sA[NN][NN + 1], sX[NN][NN + 1], sT2[NN][NN + 1];
    __shared__ float prow[2][2 * NN];
    __shared__ float sf[2][NN];
    __shared__ float smp1[NN];

    const float* Ab = A + ((size_t)b * TT + t) * NN * NN;
    for (int idx = tid; idx < NN * NN; idx += 256) {
        sSf[idx >> 5][idx & 31] = g_Sigf[b][t][idx >> 5][idx & 31];
        sA[idx >> 5][idx & 31]  = Ab[idx];
    }
    if (tid < NN) smp1[tid] = g_mup[b][t + 1][tid];
    __syncthreads();

    // X = Sigf @ A^T
    {
        float a00 = 0.f, a01 = 0.f, a10 = 0.f, a11 = 0.f;
        #pragma unroll
        for (int k = 0; k < NN; ++k) {
            const float l0 = sSf[ty][k], l1 = sSf[ty + 16][k];
            const float r0 = sA[tx][k],  r1 = sA[tx + 16][k];
            a00 += l0 * r0; a01 += l0 * r1; a10 += l1 * r0; a11 += l1 * r1;
        }
        sX[ty][tx] = a00;      sX[ty][tx + 16] = a01;
        sX[ty + 16][tx] = a10; sX[ty + 16][tx + 16] = a11;
    }
    __syncthreads();

    // Gauss-Jordan on [Sigp_{t+1} | X^T]
    const int row = tid >> 3;
    const int c0  = (tid & 7) * 8;
    float r8[8];
    if (c0 < NN) {
        #pragma unroll
        for (int m = 0; m < 8; ++m) r8[m] = g_Sigp[b][t + 1][row][c0 + m];
    } else {
        #pragma unroll
        for (int m = 0; m < 8; ++m) r8[m] = sX[c0 - NN + m][row];   // X^T
    }
    #pragma unroll
    for (int k = 0; k < NN; ++k) {
        const int pb = k & 1;
        if (row == k) {
            #pragma unroll
            for (int m = 0; m < 8; ++m) prow[pb][c0 + m] = r8[m];
        }
        if ((tid & 7) == (k >> 3)) sf[pb][row] = r8[k & 7];
        __syncthreads();
        const float pr = 1.0f / prow[pb][k];
        if (row == k) {
            #pragma unroll
            for (int m = 0; m < 8; ++m) r8[m] *= pr;
        } else {
            const float g = sf[pb][row] * pr;
            #pragma unroll
            for (int m = 0; m < 8; ++m) r8[m] -= g * prow[pb][c0 + m];
        }
    }
    __syncthreads();
    if (c0 >= NN) {
        #pragma unroll
        for (int m = 0; m < 8; ++m) sX[c0 - NN + m][row] = r8[m];   // J
    }
    __syncthreads();
    for (int idx = tid; idx < NN * NN; idx += 256) {
        g_J[b][t][idx >> 5][idx & 31] = sX[idx >> 5][idx & 31];
        sA[idx >> 5][idx & 31] = g_Sigp[b][t + 1][idx >> 5][idx & 31];
    }
    __syncthreads();

    // T2 = J @ Sigp_{t+1}
    {
        float a00 = 0.f, a01 = 0.f, a10 = 0.f, a11 = 0.f;
        #pragma unroll
        for (int k = 0; k < NN; ++k) {
            const float l0 = sX[ty][k], l1 = sX[ty + 16][k];
            const float r0 = sA[k][tx], r1 = sA[k][tx + 16];
            a00 += l0 * r0; a01 += l0 * r1; a10 += l1 * r0; a11 += l1 * r1;
        }
        sT2[ty][tx] = a00;      sT2[ty][tx + 16] = a01;
        sT2[ty + 16][tx] = a10; sT2[ty + 16][tx + 16] = a11;
    }
    __syncthreads();

    // G = Sf - T2 @ J^T ; mb = muf - J mp1
    {
        float e00 = 0.f, e01 = 0.f, e10 = 0.f, e11 = 0.f;
        #pragma unroll
        for (int k = 0; k < NN; ++k) {
            const float t0 = sT2[ty][k], t1 = sT2[ty + 16][k];
            const float j0 = sX[tx][k],  j1 = sX[tx + 16][k];
            e00 += t0 * j0; e01 += t0 * j1; e10 += t1 * j0; e11 += t1 * j1;
        }
        float* gg = &g_G[b][t][0][0];
        gg[ty * NN + tx]             = sSf[ty][tx]           - e00;
        gg[ty * NN + tx + 16]        = sSf[ty][tx + 16]      - e01;
        gg[(ty + 16) * NN + tx]      = sSf[ty + 16][tx]      - e10;
        gg[(ty + 16) * NN + tx + 16] = sSf[ty + 16][tx + 16] - e11;
    }
    if (tid < NN) {
        float m = g_muf[b][t][tid];
        #pragma unroll
        for (int k = 0; k < NN; ++k) m -= sX[tid][k] * smp1[k];
        g_mb[b][t][tid] = m;
    }
}

// ===== pair2: stride-2 composites at odd t = 2u+1 (u=0..62), fully parallel =====
// J2 = J_t J_{t+1}; G2 = G_t + J_t G_{t+1} J_t^T; mb2 = mb_t + J_t mb_{t+1}
__global__ void __launch_bounds__(256) pair2_kernel()
{
    const int t = 2 * blockIdx.x + 1;
    const int b = blockIdx.y;
    const int tid = threadIdx.x;
    const int tx = tid & 15, ty = tid >> 4;

    __shared__ float sJ[NN][NN + 1], sJn[NN][NN + 1], sGn[NN][NN + 1], sT[NN][NN + 1];
    __shared__ float smbn[NN];

    for (int idx = tid; idx < NN * NN; idx += 256) {
        const int i = idx >> 5, j = idx & 31;
        sJ[i][j]  = g_J[b][t][i][j];
        sJn[i][j] = g_J[b][t + 1][i][j];
        sGn[i][j] = g_G[b][t + 1][i][j];
    }
    if (tid < NN) smbn[tid] = g_mb[b][t + 1][tid];
    __syncthreads();

    // J2 = J @ Jn ; T = J @ Gn   (8 outputs/thread)
    {
        float a00 = 0.f, a01 = 0.f, a10 = 0.f, a11 = 0.f;
        float b00 = 0.f, b01 = 0.f, b10 = 0.f, b11 = 0.f;
        #pragma unroll
        for (int k = 0; k < NN; ++k) {
            const float l0 = sJ[ty][k], l1 = sJ[ty + 16][k];
            const float r0 = sJn[k][tx], r1 = sJn[k][tx + 16];
            const float g0 = sGn[k][tx], g1 = sGn[k][tx + 16];
            a00 += l0 * r0; a01 += l0 * r1; a10 += l1 * r0; a11 += l1 * r1;
            b00 += l0 * g0; b01 += l0 * g1; b10 += l1 * g0; b11 += l1 * g1;
        }
        float* j2 = &g_J2[b][t][0][0];
        j2[ty * NN + tx] = a00;        j2[ty * NN + tx + 16] = a01;
        j2[(ty + 16) * NN + tx] = a10; j2[(ty + 16) * NN + tx + 16] = a11;
        sT[ty][tx] = b00;      sT[ty][tx + 16] = b01;
        sT[ty + 16][tx] = b10; sT[ty + 16][tx + 16] = b11;
    }
    if (tid < NN) {
        float m = g_mb[b][t][tid];
        #pragma unroll
        for (int k = 0; k < NN; ++k) m += sJ[tid][k] * smbn[k];
        g_mb2[b][t][tid] = m;
    }
    __syncthreads();

    // G2 = G_t + T @ J^T
    {
        float e00 = 0.f, e01 = 0.f, e10 = 0.f, e11 = 0.f;
        #pragma unroll
        for (int k = 0; k < NN; ++k) {
            const float t0 = sT[ty][k], t1 = sT[ty + 16][k];
            const float j0 = sJ[tx][k], j1 = sJ[tx + 16][k];
            e00 += t0 * j0; e01 += t0 * j1; e10 += t1 * j0; e11 += t1 * j1;
        }
        float* g2 = &g_G2[b][t][0][0];
        g2[ty * NN + tx]             = g_G[b][t][ty][tx]           + e00;
        g2[ty * NN + tx + 16]        = g_G[b][t][ty][tx + 16]      + e01;
        g2[(ty + 16) * NN + tx]      = g_G[b][t][ty + 16][tx]      + e10;
        g2[(ty + 16) * NN + tx + 16] = g_G[b][t][ty + 16][tx + 16] + e11;
    }
}

// ===== pair4: stride-4 composites at t = 4v+3 (v=0..30) from stride-2 =====
__global__ void __launch_bounds__(256) pair4_kernel()
{
    const int t = 4 * blockIdx.x + 3;
    const int b = blockIdx.y;
    const int tid = threadIdx.x;
    const int tx = tid & 15, ty = tid >> 4;

    __shared__ float sJ[NN][NN + 1], sJn[NN][NN + 1], sGn[NN][NN + 1], sT[NN][NN + 1];
    __shared__ float smbn[NN];

    for (int idx = tid; idx < NN * NN; idx += 256) {
        const int i = idx >> 5, j = idx & 31;
        sJ[i][j]  = g_J2[b][t][i][j];
        sJn[i][j] = g_J2[b][t + 2][i][j];
        sGn[i][j] = g_G2[b][t + 2][i][j];
    }
    if (tid < NN) smbn[tid] = g_mb2[b][t + 2][tid];
    __syncthreads();

    {
        float a00 = 0.f, a01 = 0.f, a10 = 0.f, a11 = 0.f;
        float b00 = 0.f, b01 = 0.f, b10 = 0.f, b11 = 0.f;
        #pragma unroll
        for (int k = 0; k < NN; ++k) {
            const float l0 = sJ[ty][k], l1 = sJ[ty + 16][k];
            const float r0 = sJn[k][tx], r1 = sJn[k][tx + 16];
            const float g0 = sGn[k][tx], g1 = sGn[k][tx + 16];
            a00 += l0 * r0; a01 += l0 * r1; a10 += l1 * r0; a11 += l1 * r1;
            b00 += l0 * g0; b01 += l0 * g1; b10 += l1 * g0; b11 += l1 * g1;
        }
        float* j4 = &g_J4[b][t][0][0];
        j4[ty * NN + tx] = a00;        j4[ty * NN + tx + 16] = a01;
        j4[(ty + 16) * NN + tx] = a10; j4[(ty + 16) * NN + tx + 16] = a11;
        sT[ty][tx] = b00;      sT[ty][tx + 16] = b01;
        sT[ty + 16][tx] = b10; sT[ty + 16][tx + 16] = b11;
    }
    if (tid < NN) {
        float m = g_mb2[b][t][tid];
        #pragma unroll
        for (int k = 0; k < NN; ++k) m += sJ[tid][k] * smbn[k];
        g_mb4[b][t][tid] = m;
    }
    __syncthreads();

    {
        float e00 = 0.f, e01 = 0.f, e10 = 0.f, e11 = 0.f;
        #pragma unroll
        for (int k = 0; k < NN; ++k) {
            const float t0 = sT[ty][k], t1 = sT[ty + 16][k];
            const float j0 = sJ[tx][k], j1 = sJ[tx + 16][k];
            e00 += t0 * j0; e01 += t0 * j1; e10 += t1 * j0; e11 += t1 * j1;
        }
        float* g4 = &g_G4[b][t][0][0];
        g4[ty * NN + tx]             = g_G2[b][t][ty][tx]           + e00;
        g4[ty * NN + tx + 16]        = g_G2[b][t][ty][tx + 16]      + e01;
        g4[(ty + 16) * NN + tx]      = g_G2[b][t][ty + 16][tx]      + e10;
        g4[(ty + 16) * NN + tx + 16] = g_G2[b][t][ty + 16][tx + 16] + e11;
    }
}

// ===== serial backward with stride-4 ops: 31 steps (t = 123, 119, ..., 3) =====
__global__ void __launch_bounds__(512) bwd4_kernel(float* __restrict__ out)
{
    const int b = blockIdx.x;
    const int tid = threadIdx.x;
    const int j  = tid & 31;
    const int i0 = tid >> 5;

    __shared__ float sJ[2][NN][NN + 1], sTmp[NN][NN + 1], sSig[NN][NN + 1];
    __shared__ float smu[NN];

    // seed t = 127
    {
        const float v0 = g_Sigf[b][TT - 1][i0][j];
        const float v1 = g_Sigf[b][TT - 1][i0 + 16][j];
        sSig[i0][j] = v0; sSig[i0 + 16][j] = v1;
        g_Sigs[b][TT - 1][i0][j] = v0; g_Sigs[b][TT - 1][i0 + 16][j] = v1;
        const size_t base = ((size_t)b * TT + (TT - 1)) * NN;
        out[(base + i0) * NP1 + 1 + j] = v0;
        out[(base + i0 + 16) * NP1 + 1 + j] = v1;
        if (tid < NN) {
            const float m = g_muf[b][TT - 1][tid];
            smu[tid] = m;
            g_mus[b][TT - 1][tid] = m;
            out[(base + tid) * NP1] = m;
        }
    }
    float pG0 = g_G4[b][123][i0][j];
    float pG1 = g_G4[b][123][i0 + 16][j];
    sJ[0][i0][j]      = g_J4[b][123][i0][j];
    sJ[0][i0 + 16][j] = g_J4[b][123][i0 + 16][j];
    __syncthreads();

    int cur = 0;
    for (int v = 30; v >= 0; --v) {
        const int t = 4 * v + 3;
        // phase 1: tmp = J4 @ Sig ; mu (regs) ; prefetch next
        float a0 = 0.f, a1 = 0.f;
        #pragma unroll
        for (int k = 0; k < NN; ++k) {
            const float r = sSig[k][j];
            a0 += sJ[cur][i0][k] * r; a1 += sJ[cur][i0 + 16][k] * r;
        }
        sTmp[i0][j] = a0; sTmp[i0 + 16][j] = a1;

        float m = 0.f;
        if (tid < NN) {
            m = g_mb4[b][t][tid];
            #pragma unroll
            for (int k = 0; k < NN; ++k) m += sJ[cur][tid][k] * smu[k];
        }
        float nJ0 = 0.f, nJ1 = 0.f, nG0 = 0.f, nG1 = 0.f;
        if (v > 0) {
            nJ0 = g_J4[b][t - 4][i0][j];     nJ1 = g_J4[b][t - 4][i0 + 16][j];
            nG0 = g_G4[b][t - 4][i0][j];     nG1 = g_G4[b][t - 4][i0 + 16][j];
        }
        __syncthreads();

        // phase 2: Sig = G4 + tmp @ J4^T ; emit
        {
            float e0 = 0.f, e1 = 0.f;
            #pragma unroll
            for (int k = 0; k < NN; ++k) {
                const float jj = sJ[cur][j][k];
                e0 += sTmp[i0][k] * jj; e1 += sTmp[i0 + 16][k] * jj;
            }
            const float v0 = pG0 + e0;
            const float v1 = pG1 + e1;
            sSig[i0][j] = v0; sSig[i0 + 16][j] = v1;
            g_Sigs[b][t][i0][j] = v0; g_Sigs[b][t][i0 + 16][j] = v1;
            const size_t base = ((size_t)b * TT + t) * NN;
            out[(base + i0) * NP1 + 1 + j] = v0;
            out[(base + i0 + 16) * NP1 + 1 + j] = v1;
            if (tid < NN) {
                smu[tid] = m;
                g_mus[b][t][tid] = m;
                out[(base + tid) * NP1] = m;
            }
        }
        if (v > 0) {
            sJ[cur ^ 1][i0][j] = nJ0; sJ[cur ^ 1][i0 + 16][j] = nJ1;
            pG0 = nG0; pG1 = nG1;
        }
        __syncthreads();
        cur ^= 1;
    }
}

// ===== fillA: t = 4w+1 (w=0..31) via stride-2 ops; parallel =====
__global__ void __launch_bounds__(256) fillA_kernel(float* __restrict__ out)
{
    const int t = 4 * blockIdx.x + 1;
    const int b = blockIdx.y;
    const int tid = threadIdx.x;
    const int tx = tid & 15, ty = tid >> 4;

    __shared__ float sJ[NN][NN + 1], sS[NN][NN + 1], sT[NN][NN + 1];
    __shared__ float smun[NN];

    for (int idx = tid; idx < NN * NN; idx += 256) {
        const int i = idx >> 5, j = idx & 31;
        sJ[i][j] = g_J2[b][t][i][j];
        sS[i][j] = g_Sigs[b][t + 2][i][j];
    }
    if (tid < NN) smun[tid] = g_mus[b][t + 2][tid];
    __syncthreads();

    {
        float a00 = 0.f, a01 = 0.f, a10 = 0.f, a11 = 0.f;
        #pragma unroll
        for (int k = 0; k < NN; ++k) {
            const float l0 = sJ[ty][k], l1 = sJ[ty + 16][k];
            const float r0 = sS[k][tx], r1 = sS[k][tx + 16];
            a00 += l0 * r0; a01 += l0 * r1; a10 += l1 * r0; a11 += l1 * r1;
        }
        sT[ty][tx] = a00;      sT[ty][tx + 16] = a01;
        sT[ty + 16][tx] = a10; sT[ty + 16][tx + 16] = a11;
    }
    __syncthreads();
    {
        float e00 = 0.f, e01 = 0.f, e10 = 0.f, e11 = 0.f;
        #pragma unroll
        for (int k = 0; k < NN; ++k) {
            const float t0 = sT[ty][k], t1 = sT[ty + 16][k];
            const float j0 = sJ[tx][k], j1 = sJ[tx + 16][k];
            e00 += t0 * j0; e01 += t0 * j1; e10 += t1 * j0; e11 += t1 * j1;
        }
        const float v00 = g_G2[b][t][ty][tx]           + e00;
        const float v01 = g_G2[b][t][ty][tx + 16]      + e01;
        const float v10 = g_G2[b][t][ty + 16][tx]      + e10;
        const float v11 = g_G2[b][t][ty + 16][tx + 16] + e11;
        g_Sigs[b][t][ty][tx] = v00;        g_Sigs[b][t][ty][tx + 16] = v01;
        g_Sigs[b][t][ty + 16][tx] = v10;   g_Sigs[b][t][ty + 16][tx + 16] = v11;
        const size_t base = ((size_t)b * TT + t) * NN;
        out[(base + ty) * NP1 + 1 + tx]           = v00;
        out[(base + ty) * NP1 + 1 + tx + 16]      = v01;
        out[(base + ty + 16) * NP1 + 1 + tx]      = v10;
        out[(base + ty + 16) * NP1 + 1 + tx + 16] = v11;
    }
    if (tid < NN) {
        float m = g_mb2[b][t][tid];
        #pragma unroll
        for (int k = 0; k < NN; ++k) m += sJ[tid][k] * smun[k];
        g_mus[b][t][tid] = m;
        out[(((size_t)b * TT + t) * NN + tid) * NP1] = m;
    }
}

// ===== fillB: even t (0..126) via stride-1 ops; parallel =====
__global__ void __launch_bounds__(256) fillB_kernel(float* __restrict__ out)
{
    const int t = 2 * blockIdx.x;
    const int b = blockIdx.y;
    const int tid = threadIdx.x;
    const int tx = tid & 15, ty = tid >> 4;

    __shared__ float sJ[NN][NN + 1], sS[NN][NN + 1], sT[NN][NN + 1];
    __shared__ float smun[NN];

    for (int idx = tid; idx < NN * NN; idx += 256) {
        const int i = idx >> 5, j = idx & 31;
        sJ[i][j] = g_J[b][t][i][j];
        sS[i][j] = g_Sigs[b][t + 1][i][j];
    }
    if (tid < NN) smun[tid] = g_mus[b][t + 1][tid];
    __syncthreads();

    {
        float a00 = 0.f, a01 = 0.f, a10 = 0.f, a11 = 0.f;
        #pragma unroll
        for (int k = 0; k < NN; ++k) {
            const float l0 = sJ[ty][k], l1 = sJ[ty + 16][k];
            const float r0 = sS[k][tx], r1 = sS[k][tx + 16];
            a00 += l0 * r0; a01 += l0 * r1; a10 += l1 * r0; a11 += l1 * r1;
        }
        sT[ty][tx] = a00;      sT[ty][tx + 16] = a01;
        sT[ty + 16][tx] = a10; sT[ty + 16][tx + 16] = a11;
    }
    __syncthreads();
    {
        float e00 = 0.f, e01 = 0.f, e10 = 0.f, e11 = 0.f;
        #pragma unroll
        for (int k = 0; k < NN; ++k) {
            const float t0 = sT[ty][k], t1 = sT[ty + 16][k];
            const float j0 = sJ[tx][k], j1 = sJ[tx + 16][k];
            e00 += t0 * j0; e01 += t0 * j1; e10 += t1 * j0; e11 += t1 * j1;
        }
        const size_t base = ((size_t)b * TT + t) * NN;
        out[(base + ty) * NP1 + 1 + tx]           = g_G[b][t][ty][tx]           + e00;
        out[(base + ty) * NP1 + 1 + tx + 16]      = g_G[b][t][ty][tx + 16]      + e01;
        out[(base + ty + 16) * NP1 + 1 + tx]      = g_G[b][t][ty + 16][tx]      + e10;
        out[(base + ty + 16) * NP1 + 1 + tx + 16] = g_G[b][t][ty + 16][tx + 16] + e11;
    }
    if (tid < NN) {
        float m = g_mb[b][t][tid];
        #pragma unroll
        for (int k = 0; k < NN; ++k) m += sJ[tid][k] * smun[k];
        out[(((size_t)b * TT + t) * NN + tid) * NP1] = m;
    }
}

// ---------------- launch ----------------
extern "C" void kernel_launch(void* const* d_in, const int* in_sizes, int n_in,
                              void* d_out, int out_size)
{
    const float* Y      = (const float*)d_in[0];
    const float* U      = (const float*)d_in[1];
    const float* A      = (const float*)d_in[2];
    const float* Bm     = (const float*)d_in[3];
    const float* C      = (const float*)d_in[4];
    const float* mu0    = (const float*)d_in[5];
    const float* Sigma0 = (const float*)d_in[6];
    float* out = (float*)d_out;

    fwd_kernel<<<BB, 512>>>(Y, U, A, Bm, C, mu0, Sigma0);
    jgain_kernel<<<dim3(TT - 1, BB), 256>>>(A);
    pair2_kernel<<<dim3(63, BB), 256>>>();
    pair4_kernel<<<dim3(31, BB), 256>>>();
    bwd4_kernel<<<BB, 512>>>(out);
    fillA_kernel<<<dim3(32, BB), 256>>>(out);
    fillB_kernel<<<dim3(64, BB), 256>>>(out);
}

// round 8
// speedup vs baseline: 1.3063x; 1.0069x over previous
#include <cuda_runtime.h>

#define NN 32
#define MM 8
#define PP 16
#define BB 64
#define TT 128
#define NP1 33

// ---------------- global scratch ----------------
__device__ float g_muf[BB][TT][NN];
__device__ float g_mup[BB][TT][NN];
__device__ float g_Sigf[BB][TT][NN][NN];
__device__ float g_Sigp[BB][TT][NN][NN];
__device__ float g_J[BB][TT][NN][NN];    // t in [0, TT-2]
__device__ float g_G[BB][TT][NN][NN];    // Gs_t = Sigf_t - J Sigp_{t+1} J^T
__device__ float g_mb[BB][TT][NN];       // mb_t = muf_t - J mup_{t+1}
// stride-2 composites at odd t (1,3,...,125)
__device__ float g_J2[BB][TT][NN][NN];
__device__ float g_G2[BB][TT][NN][NN];
__device__ float g_mb2[BB][TT][NN];
// stride-4 composites at t = 3 mod 4 (3,7,...,123)
__device__ float g_J4[BB][TT][NN][NN];
__device__ float g_G4[BB][TT][NN][NN];
__device__ float g_mb4[BB][TT][NN];
// smoothed results needed by fill passes
__device__ float g_Sigs[BB][TT][NN][NN];
__device__ float g_mus[BB][TT][NN];

// ================= forward filter: 1 CTA / batch, 512 threads =================
// 4-phase software-pipelined step; CA_t = C_t A_t and C_t C_t^T computed one
// step ahead (during P4) from prefetched tiles.
__global__ void __launch_bounds__(512) fwd_kernel(
    const float* __restrict__ Y, const float* __restrict__ U,
    const float* __restrict__ A, const float* __restrict__ Bm,
    const float* __restrict__ C, const float* __restrict__ mu0,
    const float* __restrict__ Sigma0)
{
    const int b = blockIdx.x;
    const int tid = threadIdx.x;
    const int lane = tid & 31, wid = tid >> 5;
    const int g  = tid >> 8;          // 0 or 1
    const int t8 = tid & 255;
    const int tx = t8 & 15;
    const int ty = t8 >> 4;           // 0..15

    __shared__ float sA[2][NN][NN + 1], sC[2][PP][NN + 1], sB[2][NN][MM + 1];
    __shared__ float sCA[2][PP][NN + 1], sCCt[2][PP][PP + 1];
    __shared__ float sy[2][PP], su[2][MM];
    __shared__ float sSig[NN][NN + 1], sTmp[NN][NN + 1], sSigp[NN][NN + 1];
    __shared__ float sE[PP][NN + 1], sCS[PP][NN + 1], sS0[PP][PP + 1], sK[NN][PP + 1];
    __shared__ float smu[NN], smup[NN], sr[PP];

    const float* Ab = A  + (size_t)b * TT * NN * NN;
    const float* Cb = C  + (size_t)b * TT * PP * NN;
    const float* Bb = Bm + (size_t)b * TT * NN * MM;
    const float* Yb = Y  + (size_t)b * TT * PP;
    const float* Ub = U  + (size_t)b * TT * MM;

    // init: carry + buffer 0
    for (int idx = tid; idx < NN * NN; idx += 512) {
        sSig[idx >> 5][idx & 31]  = Sigma0[idx];
        sA[0][idx >> 5][idx & 31] = Ab[idx];
    }
    for (int idx = tid; idx < PP * NN; idx += 512) sC[0][idx >> 5][idx & 31] = Cb[idx];
    if (tid < NN * MM) sB[0][tid >> 3][tid & 7] = Bb[tid];
    if (tid < NN) smu[tid] = mu0[tid];
    if (tid < PP) sy[0][tid] = Yb[tid];
    else if (tid < PP + MM) su[0][tid - PP] = Ub[tid - PP];
    __syncthreads();
    // init CA_0, CCt_0 (256 threads suffice; use g1 half to mirror loop shape)
    if (g == 1) {
        float ca0 = 0.f, ca1 = 0.f, cc = 0.f;
        #pragma unroll
        for (int k = 0; k < NN; ++k) {
            const float c = sC[0][ty][k];
            ca0 += c * sA[0][k][tx]; ca1 += c * sA[0][k][tx + 16];
            cc  += c * sC[0][tx][k];
        }
        sCA[0][ty][tx] = ca0; sCA[0][ty][tx + 16] = ca1;
        sCCt[0][ty][tx] = cc;
    }
    __syncthreads();

    for (int t = 0; t < TT; ++t) {
        const int cur = t & 1, nxt = cur ^ 1;

        // ==== P1: g0: tmp = A@Sig (2x2) | g1: E = CA@Sig ; mup ====
        if (g == 0) {
            float a00 = 0.f, a01 = 0.f, a10 = 0.f, a11 = 0.f;
            #pragma unroll
            for (int k = 0; k < NN; ++k) {
                const float l0 = sA[cur][ty][k],  l1 = sA[cur][ty + 16][k];
                const float r0 = sSig[k][tx],     r1 = sSig[k][tx + 16];
                a00 += l0 * r0; a01 += l0 * r1; a10 += l1 * r0; a11 += l1 * r1;
            }
            sTmp[ty][tx] = a00;      sTmp[ty][tx + 16] = a01;
            sTmp[ty + 16][tx] = a10; sTmp[ty + 16][tx + 16] = a11;
        } else {
            float e0 = 0.f, e1 = 0.f;
            #pragma unroll
            for (int k = 0; k < NN; ++k) {
                const float cv = sCA[cur][ty][k];
                e0 += cv * sSig[k][tx]; e1 += cv * sSig[k][tx + 16];
            }
            sE[ty][tx] = e0; sE[ty][tx + 16] = e1;
            if (tid >= 480) {
                const int l = tid - 480;
                float m = 0.f;
                #pragma unroll
                for (int k = 0; k < NN; ++k) m += sA[cur][l][k] * smu[k];
                #pragma unroll
                for (int k = 0; k < MM; ++k) m += sB[cur][l][k] * su[cur][k];
                smup[l] = m;
            }
        }
        __syncthreads();

        // ==== P2: g0: Sigp = tmp@A^T + Q | g1: CS = E@A^T+0.01C ; S0 = E@CA^T+0.01CCt ; r ====
        if (g == 0) {
            float a00 = 0.f, a01 = 0.f, a10 = 0.f, a11 = 0.f;
            #pragma unroll
            for (int k = 0; k < NN; ++k) {
                const float l0 = sTmp[ty][k],     l1 = sTmp[ty + 16][k];
                const float r0 = sA[cur][tx][k],  r1 = sA[cur][tx + 16][k];
                a00 += l0 * r0; a01 += l0 * r1; a10 += l1 * r0; a11 += l1 * r1;
            }
            const float q = (ty == tx) ? 0.01f : 0.f;
            a00 += q; a11 += q;
            sSigp[ty][tx] = a00;      sSigp[ty][tx + 16] = a01;
            sSigp[ty + 16][tx] = a10; sSigp[ty + 16][tx + 16] = a11;
            float* gp = &g_Sigp[b][t][0][0];
            gp[ty * NN + tx] = a00;        gp[ty * NN + tx + 16] = a01;
            gp[(ty + 16) * NN + tx] = a10; gp[(ty + 16) * NN + tx + 16] = a11;
        } else {
            float cs0 = 0.f, cs1 = 0.f, s0 = 0.f;
            #pragma unroll
            for (int k = 0; k < NN; ++k) {
                const float e = sE[ty][k];
                cs0 += e * sA[cur][tx][k];
                cs1 += e * sA[cur][tx + 16][k];
                s0  += e * sCA[cur][tx][k];
            }
            sCS[ty][tx]      = cs0 + 0.01f * sC[cur][ty][tx];
            sCS[ty][tx + 16] = cs1 + 0.01f * sC[cur][ty][tx + 16];
            sS0[ty][tx]      = s0  + 0.01f * sCCt[cur][ty][tx];
            if (tid >= 480 && tid < 480 + PP) {
                const int i = tid - 480;
                float m = 0.f;
                #pragma unroll
                for (int k = 0; k < NN; ++k) m += sC[cur][i][k] * smup[k];
                sr[i] = sy[cur][i] - m;
            }
        }
        __syncthreads();

        // ==== P3: warp0 GJ on [sym(S0)+R | CS] -> K ; warps 1-15 load next inputs ====
        if (wid == 0) {
            float colA[PP], colB[PP];
            #pragma unroll
            for (int i = 0; i < PP; ++i) {
                colA[i] = (lane < PP)
                    ? 0.5f * (sS0[i][lane] + sS0[lane][i]) + ((i == lane) ? 0.01f : 0.f)
                    : sCS[i][lane - PP];
                colB[i] = (lane < PP) ? sCS[i][PP + lane] : 0.f;
            }
            #pragma unroll
            for (int k = 0; k < PP; ++k) {
                float f[PP];
                #pragma unroll
                for (int i = 0; i < PP; ++i) f[i] = __shfl_sync(0xffffffffu, colA[i], k);
                const float pr = 1.0f / f[k];
                #pragma unroll
                for (int i = 0; i < PP; ++i) {
                    if (i != k) {
                        const float gg = f[i] * pr;
                        colA[i] -= gg * colA[k];
                        colB[i] -= gg * colB[k];
                    }
                }
                colA[k] *= pr; colB[k] *= pr;
            }
            if (lane >= PP) {
                #pragma unroll
                for (int i = 0; i < PP; ++i) sK[lane - PP][i] = colA[i];
            } else {
                #pragma unroll
                for (int i = 0; i < PP; ++i) sK[PP + lane][i] = colB[i];
            }
        } else if (t + 1 < TT) {
            const int wt = tid - 32;
            const float* An = Ab + (size_t)(t + 1) * NN * NN;
            const float* Cn = Cb + (size_t)(t + 1) * PP * NN;
            const float* Bn = Bb + (size_t)(t + 1) * NN * MM;
            for (int idx = wt; idx < NN * NN; idx += 480) sA[nxt][idx >> 5][idx & 31] = An[idx];
            for (int idx = wt; idx < PP * NN; idx += 480) sC[nxt][idx >> 5][idx & 31] = Cn[idx];
            for (int idx = wt; idx < NN * MM; idx += 480) sB[nxt][idx >> 3][idx & 7] = Bn[idx];
            if (wt < PP) sy[nxt][wt] = Yb[(t + 1) * PP + wt];
            else if (wt < PP + MM) su[nxt][wt - PP] = Ub[(t + 1) * MM + (wt - PP)];
        }
        __syncthreads();

        // ==== P4: g0: Sig_f = Sigp - K@CS | g1: CA/CCt for t+1 ; mu_f ====
        if (g == 0) {
            float x00 = sSigp[ty][tx],      x01 = sSigp[ty][tx + 16];
            float x10 = sSigp[ty + 16][tx], x11 = sSigp[ty + 16][tx + 16];
            #pragma unroll
            for (int k = 0; k < PP; ++k) {
                const float k0 = sK[ty][k],  k1 = sK[ty + 16][k];
                const float c0 = sCS[k][tx], c1 = sCS[k][tx + 16];
                x00 -= k0 * c0; x01 -= k0 * c1; x10 -= k1 * c0; x11 -= k1 * c1;
            }
            sSig[ty][tx] = x00;      sSig[ty][tx + 16] = x01;
            sSig[ty + 16][tx] = x10; sSig[ty + 16][tx + 16] = x11;
            float* gf = &g_Sigf[b][t][0][0];
            gf[ty * NN + tx] = x00;        gf[ty * NN + tx + 16] = x01;
            gf[(ty + 16) * NN + tx] = x10; gf[(ty + 16) * NN + tx + 16] = x11;
        } else {
            if (t + 1 < TT) {
                float ca0 = 0.f, ca1 = 0.f, cc = 0.f;
                #pragma unroll
                for (int k = 0; k < NN; ++k) {
                    const float c = sC[nxt][ty][k];
                    ca0 += c * sA[nxt][k][tx]; ca1 += c * sA[nxt][k][tx + 16];
                    cc  += c * sC[nxt][tx][k];
                }
                sCA[nxt][ty][tx] = ca0; sCA[nxt][ty][tx + 16] = ca1;
                sCCt[nxt][ty][tx] = cc;
            }
            if (tid >= 480) {
                const int l = tid - 480;
                float m = smup[l];
                #pragma unroll
                for (int k = 0; k < PP; ++k) m += sK[l][k] * sr[k];
                smu[l] = m;
                g_muf[b][t][l] = m;
                g_mup[b][t][l] = smup[l];
            }
        }
        __syncthreads();
    }
}

// ===== smoother gains + backward constants (fully parallel over b,t) =====
__global__ void __launch_bounds__(256) jgain_kernel(const float* __restrict__ A)
{
    const int t = blockIdx.x;     // 0..TT-2
    const int b = blockIdx.y;
    const int tid = threadIdx.x;
    const int tx = tid & 15, ty = tid >> 4;

    __shared__ float sSf[NN][NN + 1], sA[NN][NN + 1], sX[NN][NN + 1], sT2[NN][NN + 1];
    __shared__ float prow[2][2 * NN];
    __shared__ float sf[2][NN];
    __shared__ float smp1[NN];

    const float* Ab = A + ((size_t)b * TT + t) * NN * NN;
    for (int idx = tid; idx < NN * NN; idx += 256) {
        sSf[idx >> 5][idx & 31] = g_Sigf[b][t][idx >> 5][idx & 31];
        sA[idx >> 5][idx & 31]  = Ab[idx];
    }
    if (tid < NN) smp1[tid] = g_mup[b][t + 1][tid];
    __syncthreads();

    // X = Sigf @ A^T
    {
        float a00 = 0.f, a01 = 0.f, a10 = 0.f, a11 = 0.f;
        #pragma unroll
        for (int k = 0; k < NN; ++k) {
            const float l0 = sSf[ty][k], l1 = sSf[ty + 16][k];
            const float r0 = sA[tx][k],  r1 = sA[tx + 16][k];
            a00 += l0 * r0; a01 += l0 * r1; a10 += l1 * r0; a11 += l1 * r1;
        }
        sX[ty][tx] = a00;      sX[ty][tx + 16] = a01;
        sX[ty + 16][tx] = a10; sX[ty + 16][tx + 16] = a11;
    }
    __syncthreads();

    // Gauss-Jordan on [Sigp_{t+1} | X^T]
    const int row = tid >> 3;
    const int c0  = (tid & 7) * 8;
    float r8[8];
    if (c0 < NN) {
        #pragma unroll
        for (int m = 0; m < 8; ++m) r8[m] = g_Sigp[b][t + 1][row][c0 + m];
    } else {
        #pragma unroll
        for (int m = 0; m < 8; ++m) r8[m] = sX[c0 - NN + m][row];   // X^T
    }
    #pragma unroll
    for (int k = 0; k < NN; ++k) {
        const int pb = k & 1;
        if (row == k) {
            #pragma unroll
            for (int m = 0; m < 8; ++m) prow[pb][c0 + m] = r8[m];
        }
        if ((tid & 7) == (k >> 3)) sf[pb][row] = r8[k & 7];
        __syncthreads();
        const float pr = 1.0f / prow[pb][k];
        if (row == k) {
            #pragma unroll
            for (int m = 0; m < 8; ++m) r8[m] *= pr;
        } else {
            const float g = sf[pb][row] * pr;
            #pragma unroll
            for (int m = 0; m < 8; ++m) r8[m] -= g * prow[pb][c0 + m];
        }
    }
    __syncthreads();
    if (c0 >= NN) {
        #pragma unroll
        for (int m = 0; m < 8; ++m) sX[c0 - NN + m][row] = r8[m];   // J
    }
    __syncthreads();
    for (int idx = tid; idx < NN * NN; idx += 256) {
        g_J[b][t][idx >> 5][idx & 31] = sX[idx >> 5][idx & 31];
        sA[idx >> 5][idx & 31] = g_Sigp[b][t + 1][idx >> 5][idx & 31];
    }
    __syncthreads();

    // T2 = J @ Sigp_{t+1}
    {
        float a00 = 0.f, a01 = 0.f, a10 = 0.f, a11 = 0.f;
        #pragma unroll
        for (int k = 0; k < NN; ++k) {
            const float l0 = sX[ty][k], l1 = sX[ty + 16][k];
            const float r0 = sA[k][tx], r1 = sA[k][tx + 16];
            a00 += l0 * r0; a01 += l0 * r1; a10 += l1 * r0; a11 += l1 * r1;
        }
        sT2[ty][tx] = a00;      sT2[ty][tx + 16] = a01;
        sT2[ty + 16][tx] = a10; sT2[ty + 16][tx + 16] = a11;
    }
    __syncthreads();

    // G = Sf - T2 @ J^T ; mb = muf - J mp1
    {
        float e00 = 0.f, e01 = 0.f, e10 = 0.f, e11 = 0.f;
        #pragma unroll
        for (int k = 0; k < NN; ++k) {
            const float t0 = sT2[ty][k], t1 = sT2[ty + 16][k];
            const float j0 = sX[tx][k],  j1 = sX[tx + 16][k];
            e00 += t0 * j0; e01 += t0 * j1; e10 += t1 * j0; e11 += t1 * j1;
        }
        float* gg = &g_G[b][t][0][0];
        gg[ty * NN + tx]             = sSf[ty][tx]           - e00;
        gg[ty * NN + tx + 16]        = sSf[ty][tx + 16]      - e01;
        gg[(ty + 16) * NN + tx]      = sSf[ty + 16][tx]      - e10;
        gg[(ty + 16) * NN + tx + 16] = sSf[ty + 16][tx + 16] - e11;
    }
    if (tid < NN) {
        float m = g_muf[b][t][tid];
        #pragma unroll
        for (int k = 0; k < NN; ++k) m -= sX[tid][k] * smp1[k];
        g_mb[b][t][tid] = m;
    }
}

// ===== pair2: stride-2 composites at odd t = 2u+1 (u=0..62) =====
__global__ void __launch_bounds__(256) pair2_kernel()
{
    const int t = 2 * blockIdx.x + 1;
    const int b = blockIdx.y;
    const int tid = threadIdx.x;
    const int tx = tid & 15, ty = tid >> 4;

    __shared__ float sJ[NN][NN + 1], sJn[NN][NN + 1], sGn[NN][NN + 1], sT[NN][NN + 1];
    __shared__ float smbn[NN];

    for (int idx = tid; idx < NN * NN; idx += 256) {
        const int i = idx >> 5, j = idx & 31;
        sJ[i][j]  = g_J[b][t][i][j];
        sJn[i][j] = g_J[b][t + 1][i][j];
        sGn[i][j] = g_G[b][t + 1][i][j];
    }
    if (tid < NN) smbn[tid] = g_mb[b][t + 1][tid];
    __syncthreads();

    {
        float a00 = 0.f, a01 = 0.f, a10 = 0.f, a11 = 0.f;
        float b00 = 0.f, b01 = 0.f, b10 = 0.f, b11 = 0.f;
        #pragma unroll
        for (int k = 0; k < NN; ++k) {
            const float l0 = sJ[ty][k], l1 = sJ[ty + 16][k];
            const float r0 = sJn[k][tx], r1 = sJn[k][tx + 16];
            const float g0 = sGn[k][tx], g1 = sGn[k][tx + 16];
            a00 += l0 * r0; a01 += l0 * r1; a10 += l1 * r0; a11 += l1 * r1;
            b00 += l0 * g0; b01 += l0 * g1; b10 += l1 * g0; b11 += l1 * g1;
        }
        float* j2 = &g_J2[b][t][0][0];
        j2[ty * NN + tx] = a00;        j2[ty * NN + tx + 16] = a01;
        j2[(ty + 16) * NN + tx] = a10; j2[(ty + 16) * NN + tx + 16] = a11;
        sT[ty][tx] = b00;      sT[ty][tx + 16] = b01;
        sT[ty + 16][tx] = b10; sT[ty + 16][tx + 16] = b11;
    }
    if (tid < NN) {
        float m = g_mb[b][t][tid];
        #pragma unroll
        for (int k = 0; k < NN; ++k) m += sJ[tid][k] * smbn[k];
        g_mb2[b][t][tid] = m;
    }
    __syncthreads();

    {
        float e00 = 0.f, e01 = 0.f, e10 = 0.f, e11 = 0.f;
        #pragma unroll
        for (int k = 0; k < NN; ++k) {
            const float t0 = sT[ty][k], t1 = sT[ty + 16][k];
            const float j0 = sJ[tx][k], j1 = sJ[tx + 16][k];
            e00 += t0 * j0; e01 += t0 * j1; e10 += t1 * j0; e11 += t1 * j1;
        }
        float* g2 = &g_G2[b][t][0][0];
        g2[ty * NN + tx]             = g_G[b][t][ty][tx]           + e00;
        g2[ty * NN + tx + 16]        = g_G[b][t][ty][tx + 16]      + e01;
        g2[(ty + 16) * NN + tx]      = g_G[b][t][ty + 16][tx]      + e10;
        g2[(ty + 16) * NN + tx + 16] = g_G[b][t][ty + 16][tx + 16] + e11;
    }
}

// ===== pair4: stride-4 composites at t = 4v+3 (v=0..30) =====
__global__ void __launch_bounds__(256) pair4_kernel()
{
    const int t = 4 * blockIdx.x + 3;
    const int b = blockIdx.y;
    const int tid = threadIdx.x;
    const int tx = tid & 15, ty = tid >> 4;

    __shared__ float sJ[NN][NN + 1], sJn[NN][NN + 1], sGn[NN][NN + 1], sT[NN][NN + 1];
    __shared__ float smbn[NN];

    for (int idx = tid; idx < NN * NN; idx += 256) {
        const int i = idx >> 5, j = idx & 31;
        sJ[i][j]  = g_J2[b][t][i][j];
        sJn[i][j] = g_J2[b][t + 2][i][j];
        sGn[i][j] = g_G2[b][t + 2][i][j];
    }
    if (tid < NN) smbn[tid] = g_mb2[b][t + 2][tid];
    __syncthreads();

    {
        float a00 = 0.f, a01 = 0.f, a10 = 0.f, a11 = 0.f;
        float b00 = 0.f, b01 = 0.f, b10 = 0.f, b11 = 0.f;
        #pragma unroll
        for (int k = 0; k < NN; ++k) {
            const float l0 = sJ[ty][k], l1 = sJ[ty + 16][k];
            const float r0 = sJn[k][tx], r1 = sJn[k][tx + 16];
            const float g0 = sGn[k][tx], g1 = sGn[k][tx + 16];
            a00 += l0 * r0; a01 += l0 * r1; a10 += l1 * r0; a11 += l1 * r1;
            b00 += l0 * g0; b01 += l0 * g1; b10 += l1 * g0; b11 += l1 * g1;
        }
        float* j4 = &g_J4[b][t][0][0];
        j4[ty * NN + tx] = a00;        j4[ty * NN + tx + 16] = a01;
        j4[(ty + 16) * NN + tx] = a10; j4[(ty + 16) * NN + tx + 16] = a11;
        sT[ty][tx] = b00;      sT[ty][tx + 16] = b01;
        sT[ty + 16][tx] = b10; sT[ty + 16][tx + 16] = b11;
    }
    if (tid < NN) {
        float m = g_mb2[b][t][tid];
        #pragma unroll
        for (int k = 0; k < NN; ++k) m += sJ[tid][k] * smbn[k];
        g_mb4[b][t][tid] = m;
    }
    __syncthreads();

    {
        float e00 = 0.f, e01 = 0.f, e10 = 0.f, e11 = 0.f;
        #pragma unroll
        for (int k = 0; k < NN; ++k) {
            const float t0 = sT[ty][k], t1 = sT[ty + 16][k];
            const float j0 = sJ[tx][k], j1 = sJ[tx + 16][k];
            e00 += t0 * j0; e01 += t0 * j1; e10 += t1 * j0; e11 += t1 * j1;
        }
        float* g4 = &g_G4[b][t][0][0];
        g4[ty * NN + tx]             = g_G2[b][t][ty][tx]           + e00;
        g4[ty * NN + tx + 16]        = g_G2[b][t][ty][tx + 16]      + e01;
        g4[(ty + 16) * NN + tx]      = g_G2[b][t][ty + 16][tx]      + e10;
        g4[(ty + 16) * NN + tx + 16] = g_G2[b][t][ty + 16][tx + 16] + e11;
    }
}

// ===== serial backward with stride-4 ops: 31 steps =====
__global__ void __launch_bounds__(512) bwd4_kernel(float* __restrict__ out)
{
    const int b = blockIdx.x;
    const int tid = threadIdx.x;
    const int j  = tid & 31;
    const int i0 = tid >> 5;

    __shared__ float sJ[2][NN][NN + 1], sTmp[NN][NN + 1], sSig[NN][NN + 1];
    __shared__ float smu[NN];

    {
        const float v0 = g_Sigf[b][TT - 1][i0][j];
        const float v1 = g_Sigf[b][TT - 1][i0 + 16][j];
        sSig[i0][j] = v0; sSig[i0 + 16][j] = v1;
        g_Sigs[b][TT - 1][i0][j] = v0; g_Sigs[b][TT - 1][i0 + 16][j] = v1;
        const size_t base = ((size_t)b * TT + (TT - 1)) * NN;
        out[(base + i0) * NP1 + 1 + j] = v0;
        out[(base + i0 + 16) * NP1 + 1 + j] = v1;
        if (tid < NN) {
            const float m = g_muf[b][TT - 1][tid];
            smu[tid] = m;
            g_mus[b][TT - 1][tid] = m;
            out[(base + tid) * NP1] = m;
        }
    }
    float pG0 = g_G4[b][123][i0][j];
    float pG1 = g_G4[b][123][i0 + 16][j];
    sJ[0][i0][j]      = g_J4[b][123][i0][j];
    sJ[0][i0 + 16][j] = g_J4[b][123][i0 + 16][j];
    __syncthreads();

    int cur = 0;
    for (int v = 30; v >= 0; --v) {
        const int t = 4 * v + 3;
        float a0 = 0.f, a1 = 0.f;
        #pragma unroll
        for (int k = 0; k < NN; ++k) {
            const float r = sSig[k][j];
            a0 += sJ[cur][i0][k] * r; a1 += sJ[cur][i0 + 16][k] * r;
        }
        sTmp[i0][j] = a0; sTmp[i0 + 16][j] = a1;

        float m = 0.f;
        if (tid < NN) {
            m = g_mb4[b][t][tid];
            #pragma unroll
            for (int k = 0; k < NN; ++k) m += sJ[cur][tid][k] * smu[k];
        }
        float nJ0 = 0.f, nJ1 = 0.f, nG0 = 0.f, nG1 = 0.f;
        if (v > 0) {
            nJ0 = g_J4[b][t - 4][i0][j];     nJ1 = g_J4[b][t - 4][i0 + 16][j];
            nG0 = g_G4[b][t - 4][i0][j];     nG1 = g_G4[b][t - 4][i0 + 16][j];
        }
        __syncthreads();

        {
            float e0 = 0.f, e1 = 0.f;
            #pragma unroll
            for (int k = 0; k < NN; ++k) {
                const float jj = sJ[cur][j][k];
                e0 += sTmp[i0][k] * jj; e1 += sTmp[i0 + 16][k] * jj;
            }
            const float v0 = pG0 + e0;
            const float v1 = pG1 + e1;
            sSig[i0][j] = v0; sSig[i0 + 16][j] = v1;
            g_Sigs[b][t][i0][j] = v0; g_Sigs[b][t][i0 + 16][j] = v1;
            const size_t base = ((size_t)b * TT + t) * NN;
            out[(base + i0) * NP1 + 1 + j] = v0;
            out[(base + i0 + 16) * NP1 + 1 + j] = v1;
            if (tid < NN) {
                smu[tid] = m;
                g_mus[b][t][tid] = m;
                out[(base + tid) * NP1] = m;
            }
        }
        if (v > 0) {
            sJ[cur ^ 1][i0][j] = nJ0; sJ[cur ^ 1][i0 + 16][j] = nJ1;
            pG0 = nG0; pG1 = nG1;
        }
        __syncthreads();
        cur ^= 1;
    }
}

// ===== fillA: t = 4w+1 via stride-2 ops =====
__global__ void __launch_bounds__(256) fillA_kernel(float* __restrict__ out)
{
    const int t = 4 * blockIdx.x + 1;
    const int b = blockIdx.y;
    const int tid = threadIdx.x;
    const int tx = tid & 15, ty = tid >> 4;

    __shared__ float sJ[NN][NN + 1], sS[NN][NN + 1], sT[NN][NN + 1];
    __shared__ float smun[NN];

    for (int idx = tid; idx < NN * NN; idx += 256) {
        const int i = idx >> 5, j = idx & 31;
        sJ[i][j] = g_J2[b][t][i][j];
        sS[i][j] = g_Sigs[b][t + 2][i][j];
    }
    if (tid < NN) smun[tid] = g_mus[b][t + 2][tid];
    __syncthreads();

    {
        float a00 = 0.f, a01 = 0.f, a10 = 0.f, a11 = 0.f;
        #pragma unroll
        for (int k = 0; k < NN; ++k) {
            const float l0 = sJ[ty][k], l1 = sJ[ty + 16][k];
            const float r0 = sS[k][tx], r1 = sS[k][tx + 16];
            a00 += l0 * r0; a01 += l0 * r1; a10 += l1 * r0; a11 += l1 * r1;
        }
        sT[ty][tx] = a00;      sT[ty][tx + 16] = a01;
        sT[ty + 16][tx] = a10; sT[ty + 16][tx + 16] = a11;
    }
    __syncthreads();
    {
        float e00 = 0.f, e01 = 0.f, e10 = 0.f, e11 = 0.f;
        #pragma unroll
        for (int k = 0; k < NN; ++k) {
            const float t0 = sT[ty][k], t1 = sT[ty + 16][k];
            const float j0 = sJ[tx][k], j1 = sJ[tx + 16][k];
            e00 += t0 * j0; e01 += t0 * j1; e10 += t1 * j0; e11 += t1 * j1;
        }
        const float v00 = g_G2[b][t][ty][tx]           + e00;
        const float v01 = g_G2[b][t][ty][tx + 16]      + e01;
        const float v10 = g_G2[b][t][ty + 16][tx]      + e10;
        const float v11 = g_G2[b][t][ty + 16][tx + 16] + e11;
        g_Sigs[b][t][ty][tx] = v00;        g_Sigs[b][t][ty][tx + 16] = v01;
        g_Sigs[b][t][ty + 16][tx] = v10;   g_Sigs[b][t][ty + 16][tx + 16] = v11;
        const size_t base = ((size_t)b * TT + t) * NN;
        out[(base + ty) * NP1 + 1 + tx]           = v00;
        out[(base + ty) * NP1 + 1 + tx + 16]      = v01;
        out[(base + ty + 16) * NP1 + 1 + tx]      = v10;
        out[(base + ty + 16) * NP1 + 1 + tx + 16] = v11;
    }
    if (tid < NN) {
        float m = g_mb2[b][t][tid];
        #pragma unroll
        for (int k = 0; k < NN; ++k) m += sJ[tid][k] * smun[k];
        g_mus[b][t][tid] = m;
        out[(((size_t)b * TT + t) * NN + tid) * NP1] = m;
    }
}

// ===== fillB: even t via stride-1 ops =====
__global__ void __launch_bounds__(256) fillB_kernel(float* __restrict__ out)
{
    const int t = 2 * blockIdx.x;
    const int b = blockIdx.y;
    const int tid = threadIdx.x;
    const int tx = tid & 15, ty = tid >> 4;

    __shared__ float sJ[NN][NN + 1], sS[NN][NN + 1], sT[NN][NN + 1];
    __shared__ float smun[NN];

    for (int idx = tid; idx < NN * NN; idx += 256) {
        const int i = idx >> 5, j = idx & 31;
        sJ[i][j] = g_J[b][t][i][j];
        sS[i][j] = g_Sigs[b][t + 1][i][j];
    }
    if (tid < NN) smun[tid] = g_mus[b][t + 1][tid];
    __syncthreads();

    {
        float a00 = 0.f, a01 = 0.f, a10 = 0.f, a11 = 0.f;
        #pragma unroll
        for (int k = 0; k < NN; ++k) {
            const float l0 = sJ[ty][k], l1 = sJ[ty + 16][k];
            const float r0 = sS[k][tx], r1 = sS[k][tx + 16];
            a00 += l0 * r0; a01 += l0 * r1; a10 += l1 * r0; a11 += l1 * r1;
        }
        sT[ty][tx] = a00;      sT[ty][tx + 16] = a01;
        sT[ty + 16][tx] = a10; sT[ty + 16][tx + 16] = a11;
    }
    __syncthreads();
    {
        float e00 = 0.f, e01 = 0.f, e10 = 0.f, e11 = 0.f;
        #pragma unroll
        for (int k = 0; k < NN; ++k) {
            const float t0 = sT[ty][k], t1 = sT[ty + 16][k];
            const float j0 = sJ[tx][k], j1 = sJ[tx + 16][k];
            e00 += t0 * j0; e01 += t0 * j1; e10 += t1 * j0; e11 += t1 * j1;
        }
        const size_t base = ((size_t)b * TT + t) * NN;
        out[(base + ty) * NP1 + 1 + tx]           = g_G[b][t][ty][tx]           + e00;
        out[(base + ty) * NP1 + 1 + tx + 16]      = g_G[b][t][ty][tx + 16]      + e01;
        out[(base + ty + 16) * NP1 + 1 + tx]      = g_G[b][t][ty + 16][tx]      + e10;
        out[(base + ty + 16) * NP1 + 1 + tx + 16] = g_G[b][t][ty + 16][tx + 16] + e11;
    }
    if (tid < NN) {
        float m = g_mb[b][t][tid];
        #pragma unroll
        for (int k = 0; k < NN; ++k) m += sJ[tid][k] * smun[k];
        out[(((size_t)b * TT + t) * NN + tid) * NP1] = m;
    }
}

// ---------------- launch ----------------
extern "C" void kernel_launch(void* const* d_in, const int* in_sizes, int n_in,
                              void* d_out, int out_size)
{
    const float* Y      = (const float*)d_in[0];
    const float* U      = (const float*)d_in[1];
    const float* A      = (const float*)d_in[2];
    const float* Bm     = (const float*)d_in[3];
    const float* C      = (const float*)d_in[4];
    const float* mu0    = (const float*)d_in[5];
    const float* Sigma0 = (const float*)d_in[6];
    float* out = (float*)d_out;

    fwd_kernel<<<BB, 512>>>(Y, U, A, Bm, C, mu0, Sigma0);
    jgain_kernel<<<dim3(TT - 1, BB), 256>>>(A);
    pair2_kernel<<<dim3(63, BB), 256>>>();
    pair4_kernel<<<dim3(31, BB), 256>>>();
    bwd4_kernel<<<BB, 512>>>(out);
    fillA_kernel<<<dim3(32, BB), 256>>>(out);
    fillB_kernel<<<dim3(64, BB), 256>>>(out);
}